// round 9
// baseline (speedup 1.0000x reference)
#include <cuda_runtime.h>

// Grouped 1x7 conv (NCHW, groups=2, shared weights) + roll(H), tensor cores
// (m16n8k8 tf32, 3xTF32 precision recovery).
//
// Kernel 1: one-time split of w into (tf32_hi, tf32_lo) uint2 scratch,
//           GEMM layout [oc][kw*24+ic], padded stride SWS=172.
// Kernel 2: block = (h, g, m-half): 48 oc x 56 pixels. 12 warps =
//           (mt 0..2) x (nq 0..3), frags per nq = {2,2,2,1} (7 total, no dup).
//           Weights cp.async'd (66KB); 2 CTAs/SM co-resident.

#define Hdim 56
#define Wdim 56
#define HW   3136
#define ICg  24
#define KW   7
#define SWS  172   // u64 stride per A row (168 used)
#define SXS  68    // u64 stride per x ic (62 used)

__device__ uint2 g_wsplit[96 * SWS];   // 132 KB scratch, GEMM layout

__device__ __forceinline__ unsigned tf32_rna(float x) {
    unsigned r;
    asm("cvt.rna.tf32.f32 %0, %1;" : "=r"(r) : "f"(x));
    return r;
}

__device__ __forceinline__ void mma_tf32(float c[4],
                                         unsigned a0, unsigned a1,
                                         unsigned a2, unsigned a3,
                                         unsigned b0, unsigned b1) {
    asm volatile(
        "mma.sync.aligned.m16n8k8.row.col.f32.tf32.tf32.f32 "
        "{%0,%1,%2,%3},{%4,%5,%6,%7},{%8,%9},{%0,%1,%2,%3};"
        : "+f"(c[0]), "+f"(c[1]), "+f"(c[2]), "+f"(c[3])
        : "r"(a0), "r"(a1), "r"(a2), "r"(a3), "r"(b0), "r"(b1));
}

__global__ __launch_bounds__(256, 4)
void split_w_kernel(const float* __restrict__ w)
{
    int i = blockIdx.x * 256 + threadIdx.x;
    if (i >= ICg * 96 * KW) return;          // 16128
    int ic = i / 672;
    int r  = i - ic * 672;
    int oc = r / 7;
    int kw = r - oc * 7;
    float v = w[i];
    unsigned hi = tf32_rna(v);
    float lo = v - __uint_as_float(hi);
    g_wsplit[oc * SWS + kw * ICg + ic] = make_uint2(hi, tf32_rna(lo));
}

__global__ __launch_bounds__(384, 2)
void conv1x7_tc3(const float* __restrict__ x,
                 const int* __restrict__ shift, float* __restrict__ out)
{
    extern __shared__ char smem[];
    uint2* sw = (uint2*)smem;                              // [48][SWS] = 66048 B
    uint2* sx = (uint2*)(smem + 48 * SWS * 8);             // [24][SXS] = 13056 B

    const int tid = threadIdx.x;
    const int h   = blockIdx.x;
    const int g   = blockIdx.y;
    const int mh  = blockIdx.z;      // m-half: oc in [mh*48, mh*48+48)

    // ---- weights: cp.async linear copy of this m-half's pre-split tile ----
    {
        const uint4* src = (const uint4*)(g_wsplit + mh * 48 * SWS);
        #pragma unroll
        for (int i = tid; i < 48 * SWS / 2; i += 384) {    // 4128 x 16B
            unsigned saddr = (unsigned)__cvta_generic_to_shared((uint4*)sw + i);
            asm volatile("cp.async.cg.shared.global [%0], [%1], 16;"
                         :: "r"(saddr), "l"(src + i));
        }
        asm volatile("cp.async.commit_group;");
    }

    // ---- stage + split padded x row: sx[ic][p] = split(x[ic][h][p-3]) ----
    const float* xrow = x + (size_t)g * (ICg * HW) + h * Wdim;
    for (int i = tid; i < ICg * 64; i += 384) {            // 1536
        int ic = i >> 6;
        int p  = i & 63;
        int wc = p - 3;
        float v = (wc >= 0 && wc < Wdim) ? xrow[ic * HW + wc] : 0.f;
        unsigned hi = tf32_rna(v);
        float lo = v - __uint_as_float(hi);
        sx[ic * SXS + p] = make_uint2(hi, tf32_rna(lo));
    }
    asm volatile("cp.async.wait_group 0;");
    __syncthreads();

    const int wid  = tid >> 5;        // 0..11
    const int mt   = wid >> 2;        // local m-tile 0..2
    const int nq   = wid & 3;         // n-quarter 0..3
    const int nf   = (nq == 3) ? 1 : 2;
    const int nt0  = nq * 2;          // frags nt0 .. nt0+nf-1
    const int lane = tid & 31;
    const int lg   = lane >> 2;       // 0..7
    const int lk   = lane & 3;        // 0..3

    const uint2* Abase = sw + (mt * 16 + lg) * SWS + lk;

    float c[2][4];
    #pragma unroll
    for (int f = 0; f < 2; f++)
        #pragma unroll
        for (int q = 0; q < 4; q++) c[f][q] = 0.f;

    #pragma unroll
    for (int kw = 0; kw < KW; kw++) {
        // ---- load all 3 k-steps' fragments for this kw ----
        uint2 A[3][4];
        #pragma unroll
        for (int ks = 0; ks < 3; ks++) {
            const int kb = kw * ICg + ks * 8;
            A[ks][0] = Abase[kb];
            A[ks][1] = Abase[kb + 8 * SWS];
            A[ks][2] = Abase[kb + 4];
            A[ks][3] = Abase[kb + 4 + 8 * SWS];
        }
        uint2 B0[3][2], B1[3][2];
        #pragma unroll
        for (int ks = 0; ks < 3; ks++) {
            const uint2* xb = sx + (ks * 8 + lk) * SXS + lg + kw + nt0 * 8;
            #pragma unroll
            for (int f = 0; f < 2; f++) {
                if (f < nf) {
                    B0[ks][f] = xb[f * 8];
                    B1[ks][f] = xb[f * 8 + 4 * SXS];
                }
            }
        }

        // ---- MMAs ordered (pass, ks, frag): same-acc reuse 6 apart ----
        #pragma unroll
        for (int ks = 0; ks < 3; ks++)
            #pragma unroll
            for (int f = 0; f < 2; f++)
                if (f < nf)
                    mma_tf32(c[f], A[ks][0].x, A[ks][1].x, A[ks][2].x, A[ks][3].x,
                             B0[ks][f].x, B1[ks][f].x);
        #pragma unroll
        for (int ks = 0; ks < 3; ks++)
            #pragma unroll
            for (int f = 0; f < 2; f++)
                if (f < nf)
                    mma_tf32(c[f], A[ks][0].x, A[ks][1].x, A[ks][2].x, A[ks][3].x,
                             B0[ks][f].y, B1[ks][f].y);
        #pragma unroll
        for (int ks = 0; ks < 3; ks++)
            #pragma unroll
            for (int f = 0; f < 2; f++)
                if (f < nf)
                    mma_tf32(c[f], A[ks][0].y, A[ks][1].y, A[ks][2].y, A[ks][3].y,
                             B0[ks][f].x, B1[ks][f].x);
    }

    // ---- roll + store ----
    const int s = *shift;
    int ho = (h + s) % Hdim;
    if (ho < 0) ho += Hdim;

    float* ob = out + (size_t)(g * 96 + mh * 48 + mt * 16 + lg) * HW
                    + ho * Wdim + (nt0 * 8 + 2 * lk);
    #pragma unroll
    for (int f = 0; f < 2; f++) {
        if (f < nf) {
            *(float2*)(ob + f * 8)          = make_float2(c[f][0], c[f][1]);
            *(float2*)(ob + 8 * HW + f * 8) = make_float2(c[f][2], c[f][3]);
        }
    }
}

extern "C" void kernel_launch(void* const* d_in, const int* in_sizes, int n_in,
                              void* d_out, int out_size)
{
    const float* x     = (const float*)d_in[0];
    const float* w     = (const float*)d_in[1];
    const int*   shift = (const int*)  d_in[2];
    float*       out   = (float*)d_out;

    split_w_kernel<<<63, 256>>>(w);    // 63*256 = 16128

    const int smem_bytes = 48 * SWS * 8 + ICg * SXS * 8;   // 66048 + 13056 = 79104
    cudaFuncSetAttribute(conv1x7_tc3,
                         cudaFuncAttributeMaxDynamicSharedMemorySize, smem_bytes);

    dim3 grid(Hdim, 2, 2);   // 56 rows x 2 groups x 2 m-halves = 224 blocks
    conv1x7_tc3<<<grid, 384, smem_bytes>>>(x, shift, out);
}

// round 10
// speedup vs baseline: 1.1775x; 1.1775x over previous
#include <cuda_runtime.h>

// Grouped 1x7 conv (NCHW, groups=2, shared weights) + roll(H), tensor cores
// (m16n8k8 tf32, 3xTF32 precision recovery).
//
// Kernel 1: one-time split of w into (tf32_hi, tf32_lo) uint2 scratch,
//           GEMM layout [oc][kw*24+ic], padded stride SWS=172.
// Kernel 2: block = (h, g, m-half): 48 oc x 56 pixels. 12 warps =
//           (mt 0..2) x (nq 0..3), frags per nq = {2,2,2,1}.
//           Weight tile (66KB) fetched by ONE cp.async.bulk (TMA bulk copy,
//           mbarrier complete_tx) -- kills the 4128-LDGSTS issue floor.

#define Hdim 56
#define Wdim 56
#define HW   3136
#define ICg  24
#define KW   7
#define SWS  172   // u64 stride per A row (168 used)
#define SXS  68    // u64 stride per x ic (62 used)

#define W_TILE_BYTES (48 * SWS * 8)              // 66048
#define SX_BYTES     (ICg * SXS * 8)             // 13056
#define MBAR_OFF     (W_TILE_BYTES + SX_BYTES)   // 79104

__device__ __align__(16) uint2 g_wsplit[96 * SWS];   // 132 KB scratch

__device__ __forceinline__ unsigned tf32_rna(float x) {
    unsigned r;
    asm("cvt.rna.tf32.f32 %0, %1;" : "=r"(r) : "f"(x));
    return r;
}

__device__ __forceinline__ void mma_tf32(float c[4],
                                         unsigned a0, unsigned a1,
                                         unsigned a2, unsigned a3,
                                         unsigned b0, unsigned b1) {
    asm volatile(
        "mma.sync.aligned.m16n8k8.row.col.f32.tf32.tf32.f32 "
        "{%0,%1,%2,%3},{%4,%5,%6,%7},{%8,%9},{%0,%1,%2,%3};"
        : "+f"(c[0]), "+f"(c[1]), "+f"(c[2]), "+f"(c[3])
        : "r"(a0), "r"(a1), "r"(a2), "r"(a3), "r"(b0), "r"(b1));
}

__global__ __launch_bounds__(256, 4)
void split_w_kernel(const float* __restrict__ w)
{
    int i = blockIdx.x * 256 + threadIdx.x;
    if (i >= ICg * 96 * KW) return;          // 16128
    int ic = i / 672;
    int r  = i - ic * 672;
    int oc = r / 7;
    int kw = r - oc * 7;
    float v = w[i];
    unsigned hi = tf32_rna(v);
    float lo = v - __uint_as_float(hi);
    g_wsplit[oc * SWS + kw * ICg + ic] = make_uint2(hi, tf32_rna(lo));
}

__global__ __launch_bounds__(384, 2)
void conv1x7_tc4(const float* __restrict__ x,
                 const int* __restrict__ shift, float* __restrict__ out)
{
    extern __shared__ char smem[];
    uint2* sw = (uint2*)smem;                              // [48][SWS]
    uint2* sx = (uint2*)(smem + W_TILE_BYTES);             // [24][SXS]

    unsigned smem_base;
    asm("{ .reg .u64 t; cvta.to.shared.u64 t, %1; cvt.u32.u64 %0, t; }"
        : "=r"(smem_base) : "l"(smem));
    const unsigned mbar = smem_base + MBAR_OFF;

    const int tid = threadIdx.x;
    const int h   = blockIdx.x;
    const int g   = blockIdx.y;
    const int mh  = blockIdx.z;      // m-half: oc in [mh*48, mh*48+48)

    // ---- weights: single TMA bulk copy of this m-half's pre-split tile ----
    if (tid == 0) {
        asm volatile("mbarrier.init.shared.b64 [%0], 1;" :: "r"(mbar) : "memory");
        asm volatile("fence.proxy.async.shared::cta;" ::: "memory");
        asm volatile("mbarrier.arrive.expect_tx.shared.b64 _, [%0], %1;"
                     :: "r"(mbar), "r"((unsigned)W_TILE_BYTES) : "memory");
        asm volatile(
            "cp.async.bulk.shared::cta.global.mbarrier::complete_tx::bytes "
            "[%0], [%1], %2, [%3];"
            :: "r"(smem_base), "l"(g_wsplit + mh * 48 * SWS),
               "r"((unsigned)W_TILE_BYTES), "r"(mbar) : "memory");
    }

    // ---- stage + split padded x row: sx[ic][p] = split(x[ic][h][p-3]) ----
    const float* xrow = x + (size_t)g * (ICg * HW) + h * Wdim;
    for (int i = tid; i < ICg * 64; i += 384) {            // 1536
        int ic = i >> 6;
        int p  = i & 63;
        int wc = p - 3;
        float v = (wc >= 0 && wc < Wdim) ? xrow[ic * HW + wc] : 0.f;
        unsigned hi = tf32_rna(v);
        float lo = v - __uint_as_float(hi);
        sx[ic * SXS + p] = make_uint2(hi, tf32_rna(lo));
    }
    __syncthreads();   // x stores visible; mbarrier init visible to all

    // wait for the bulk copy (phase 0)
    {
        unsigned done;
        asm volatile(
            "{\n\t.reg .pred p;\n\t"
            "mbarrier.try_wait.parity.acquire.cta.shared::cta.b64 p, [%1], 0;\n\t"
            "selp.b32 %0, 1, 0, p;\n\t}"
            : "=r"(done) : "r"(mbar) : "memory");
        while (!done) {
            asm volatile(
                "{\n\t.reg .pred p;\n\t"
                "mbarrier.try_wait.parity.acquire.cta.shared::cta.b64 p, [%1], 0, 0x989680;\n\t"
                "selp.b32 %0, 1, 0, p;\n\t}"
                : "=r"(done) : "r"(mbar) : "memory");
        }
    }

    const int wid  = tid >> 5;        // 0..11
    const int mt   = wid >> 2;        // local m-tile 0..2
    const int nq   = wid & 3;         // n-quarter 0..3
    const int nf   = (nq == 3) ? 1 : 2;
    const int nt0  = nq * 2;          // frags nt0 .. nt0+nf-1
    const int lane = tid & 31;
    const int lg   = lane >> 2;       // 0..7
    const int lk   = lane & 3;        // 0..3

    const uint2* Abase = sw + (mt * 16 + lg) * SWS + lk;

    float c[2][4];
    #pragma unroll
    for (int f = 0; f < 2; f++)
        #pragma unroll
        for (int q = 0; q < 4; q++) c[f][q] = 0.f;

    #pragma unroll
    for (int kw = 0; kw < KW; kw++) {
        uint2 A[3][4];
        #pragma unroll
        for (int ks = 0; ks < 3; ks++) {
            const int kb = kw * ICg + ks * 8;
            A[ks][0] = Abase[kb];
            A[ks][1] = Abase[kb + 8 * SWS];
            A[ks][2] = Abase[kb + 4];
            A[ks][3] = Abase[kb + 4 + 8 * SWS];
        }
        uint2 B0[3][2], B1[3][2];
        #pragma unroll
        for (int ks = 0; ks < 3; ks++) {
            const uint2* xb = sx + (ks * 8 + lk) * SXS + lg + kw + nt0 * 8;
            #pragma unroll
            for (int f = 0; f < 2; f++) {
                if (f < nf) {
                    B0[ks][f] = xb[f * 8];
                    B1[ks][f] = xb[f * 8 + 4 * SXS];
                }
            }
        }

        #pragma unroll
        for (int ks = 0; ks < 3; ks++)
            #pragma unroll
            for (int f = 0; f < 2; f++)
                if (f < nf)
                    mma_tf32(c[f], A[ks][0].x, A[ks][1].x, A[ks][2].x, A[ks][3].x,
                             B0[ks][f].x, B1[ks][f].x);
        #pragma unroll
        for (int ks = 0; ks < 3; ks++)
            #pragma unroll
            for (int f = 0; f < 2; f++)
                if (f < nf)
                    mma_tf32(c[f], A[ks][0].x, A[ks][1].x, A[ks][2].x, A[ks][3].x,
                             B0[ks][f].y, B1[ks][f].y);
        #pragma unroll
        for (int ks = 0; ks < 3; ks++)
            #pragma unroll
            for (int f = 0; f < 2; f++)
                if (f < nf)
                    mma_tf32(c[f], A[ks][0].y, A[ks][1].y, A[ks][2].y, A[ks][3].y,
                             B0[ks][f].x, B1[ks][f].x);
    }

    // ---- roll + store ----
    const int s = *shift;
    int ho = (h + s) % Hdim;
    if (ho < 0) ho += Hdim;

    float* ob = out + (size_t)(g * 96 + mh * 48 + mt * 16 + lg) * HW
                    + ho * Wdim + (nt0 * 8 + 2 * lk);
    #pragma unroll
    for (int f = 0; f < 2; f++) {
        if (f < nf) {
            *(float2*)(ob + f * 8)          = make_float2(c[f][0], c[f][1]);
            *(float2*)(ob + 8 * HW + f * 8) = make_float2(c[f][2], c[f][3]);
        }
    }
}

extern "C" void kernel_launch(void* const* d_in, const int* in_sizes, int n_in,
                              void* d_out, int out_size)
{
    const float* x     = (const float*)d_in[0];
    const float* w     = (const float*)d_in[1];
    const int*   shift = (const int*)  d_in[2];
    float*       out   = (float*)d_out;

    split_w_kernel<<<63, 256>>>(w);    // 63*256 = 16128

    const int smem_bytes = MBAR_OFF + 16;   // 79120
    cudaFuncSetAttribute(conv1x7_tc4,
                         cudaFuncAttributeMaxDynamicSharedMemorySize, smem_bytes);

    dim3 grid(Hdim, 2, 2);   // 56 rows x 2 groups x 2 m-halves = 224 blocks
    conv1x7_tc4<<<grid, 384, smem_bytes>>>(x, shift, out);
}